// round 1
// baseline (speedup 1.0000x reference)
#include <cuda_runtime.h>
#include <stdint.h>

// Problem constants
#define NREAL 8100   // 90*90 valid patches per image
#define NPAD  8192   // padded patch count (64 tiles of 128)
#define DREAL 147    // 3*7*7
#define DPAD  152    // padded to multiple of 8 (K-chunk)
#define NIMG  4
#define ALPHA_F 0.05f

// -------- device scratch (static __device__ arrays; allocation-free) --------
__device__ float g_XPt[NIMG * DPAD * NPAD];          // [b][d][n]  K-major patches of x
__device__ float g_YPt[NIMG * DPAD * NPAD];          // [b][d][n]  K-major patches of y
__device__ float g_X2[NIMG * NPAD];                  // ||xp_i||^2
__device__ float g_Y2[NIMG * NPAD];                  // ||yp_j||^2
__device__ unsigned int g_RM[NIMG * NPAD];           // row mins as float bits (non-neg)
__device__ float g_RINV[NIMG * NPAD];                // 1/(row_min + alpha)
__device__ float g_CM[NIMG * NPAD];                  // column mins
__device__ float g_DIST[268435456];                  // [b][j][i] 4*8192*8192 fp32 (1 GiB)

__device__ __forceinline__ float finf() { return __int_as_float(0x7f800000); }

// -------- patch extraction: [b,c,h,w] -> K-major [b][d][n], zero padded -----
__global__ void k_extract(const float* __restrict__ src, int which) {
    float* __restrict__ dst = which ? g_YPt : g_XPt;
    int idx = blockIdx.x * 256 + threadIdx.x;
    if (idx >= NIMG * DPAD * NPAD) return;
    int n    = idx & (NPAD - 1);
    int rest = idx >> 13;          // NPAD = 2^13
    int d    = rest % DPAD;
    int b    = rest / DPAD;
    float v = 0.0f;
    if (d < DREAL && n < NREAL) {
        int c  = d / 49;
        int rr = (d % 49) / 7;
        int ss = d % 7;
        int oy = n / 90;
        int ox = n - oy * 90;
        v = src[(((b * 3 + c) * 96) + oy + rr) * 96 + ox + ss];
    }
    dst[idx] = v;
}

// -------- squared norms over d (padded rows are zero -> harmless) -----------
__global__ void k_norms(int which) {
    const float* __restrict__ pt = which ? g_YPt : g_XPt;
    float* __restrict__ out      = which ? g_Y2  : g_X2;
    int idx = blockIdx.x * 256 + threadIdx.x;
    if (idx >= NIMG * NPAD) return;
    int n = idx & (NPAD - 1);
    int b = idx >> 13;
    const float* p = pt + (size_t)b * DPAD * NPAD + n;
    float s = 0.0f;
    for (int d = 0; d < DREAL; d++) {
        float v = p[(size_t)d * NPAD];
        s = fmaf(v, v, s);
    }
    out[idx] = s;
}

// -------- init row-min to +inf ---------------------------------------------
__global__ void k_init() {
    int idx = blockIdx.x * 256 + threadIdx.x;
    if (idx < NIMG * NPAD) g_RM[idx] = 0x7f800000u;
}

// -------- pass 1: fused GEMM + dist epilogue + row-min ----------------------
// C[j][i] = sum_k YPt[k][j] * XPt[k][i]; 128x128 tile, 8x8 per thread.
__global__ void __launch_bounds__(256, 2) k_gemm_pass1() {
    const int b  = blockIdx.z;
    const int i0 = blockIdx.x * 128;
    const int j0 = blockIdx.y * 128;
    __shared__ float As[8][128];   // XPt chunk (i side)
    __shared__ float Bs[8][128];   // YPt chunk (j side)

    const int tid = threadIdx.x;
    const int tx  = tid & 15;      // i sub-tile
    const int ty  = tid >> 4;      // j sub-tile
    const int lw  = tid >> 5;      // k row for global loads (0..7)
    const int lc  = (tid & 31) * 4; // col for global loads

    const float* Xg = g_XPt + (size_t)b * DPAD * NPAD + i0;
    const float* Yg = g_YPt + (size_t)b * DPAD * NPAD + j0;

    float acc[8][8];
#pragma unroll
    for (int a = 0; a < 8; a++)
#pragma unroll
        for (int c = 0; c < 8; c++) acc[a][c] = 0.0f;

    for (int kc = 0; kc < DPAD; kc += 8) {
        float4 av = *reinterpret_cast<const float4*>(Xg + (size_t)(kc + lw) * NPAD + lc);
        float4 bv = *reinterpret_cast<const float4*>(Yg + (size_t)(kc + lw) * NPAD + lc);
        __syncthreads();
        *reinterpret_cast<float4*>(&As[lw][lc]) = av;
        *reinterpret_cast<float4*>(&Bs[lw][lc]) = bv;
        __syncthreads();
#pragma unroll
        for (int k = 0; k < 8; k++) {
            float4 a0 = *reinterpret_cast<const float4*>(&As[k][tx * 8]);
            float4 a1 = *reinterpret_cast<const float4*>(&As[k][tx * 8 + 4]);
            float4 b0 = *reinterpret_cast<const float4*>(&Bs[k][ty * 8]);
            float4 b1 = *reinterpret_cast<const float4*>(&Bs[k][ty * 8 + 4]);
            float a[8]  = {a0.x, a0.y, a0.z, a0.w, a1.x, a1.y, a1.z, a1.w};
            float bb[8] = {b0.x, b0.y, b0.z, b0.w, b1.x, b1.y, b1.z, b1.w};
#pragma unroll
            for (int jj = 0; jj < 8; jj++)
#pragma unroll
                for (int ii = 0; ii < 8; ii++)
                    acc[jj][ii] = fmaf(bb[jj], a[ii], acc[jj][ii]);
        }
    }

    // Epilogue: dist = max((y2 + x2 - 2c)/D, 0); store dist[j][i]; row-min over i.
    const float invD = 1.0f / (float)DREAL;
    float x2v[8], y2v[8];
#pragma unroll
    for (int u = 0; u < 8; u++) {
        x2v[u] = g_X2[b * NPAD + i0 + tx * 8 + u];
        y2v[u] = g_Y2[b * NPAD + j0 + ty * 8 + u];
    }
    float* distg = g_DIST + ((size_t)b * NPAD + j0) * NPAD + i0;
    const int i_base = i0 + tx * 8;

#pragma unroll
    for (int jj = 0; jj < 8; jj++) {
        const int j = j0 + ty * 8 + jj;
        float dv[8];
        float rmin = finf();
#pragma unroll
        for (int ii = 0; ii < 8; ii++) {
            float d = fmaxf((y2v[jj] + x2v[ii] - 2.0f * acc[jj][ii]) * invD, 0.0f);
            dv[ii] = d;
            if (i_base + ii < NREAL) rmin = fminf(rmin, d);  // mask padded patches
        }
        float* row = distg + (size_t)(ty * 8 + jj) * NPAD + tx * 8;
        *reinterpret_cast<float4*>(row)     = make_float4(dv[0], dv[1], dv[2], dv[3]);
        *reinterpret_cast<float4*>(row + 4) = make_float4(dv[4], dv[5], dv[6], dv[7]);
        // reduce min across the 16 tx lanes sharing this j (contiguous half-warp)
#pragma unroll
        for (int off = 1; off < 16; off <<= 1)
            rmin = fminf(rmin, __shfl_xor_sync(0xffffffffu, rmin, off));
        if (tx == 0 && j < NREAL)
            atomicMin(&g_RM[b * NPAD + j], __float_as_uint(rmin)); // valid: dist >= 0
    }
}

// -------- reciprocal of (row_min + alpha) -----------------------------------
__global__ void k_rinv() {
    int idx = blockIdx.x * 256 + threadIdx.x;
    if (idx >= NIMG * NPAD) return;
    int j = idx & (NPAD - 1);
    float rm = __uint_as_float(g_RM[idx]);
    g_RINV[idx] = (j < NREAL) ? 1.0f / (rm + ALPHA_F) : 0.0f;
}

// -------- pass 2: column min of dist[j][i] * rinv[j] ------------------------
// One thread per i; warp reads 32 consecutive i at fixed j -> fully coalesced.
__global__ void k_pass2() {
    const int b = blockIdx.y;
    const int i = blockIdx.x * 256 + threadIdx.x;
    if (i >= NREAL) return;
    const float* dptr = g_DIST + (size_t)b * NPAD * NPAD + i;
    const float* rinv = g_RINV + b * NPAD;
    float m0 = finf(), m1 = finf(), m2 = finf(), m3 = finf();
    for (int j = 0; j < NREAL; j += 4) {   // NREAL % 4 == 0
        m0 = fminf(m0, dptr[(size_t)(j + 0) * NPAD] * rinv[j + 0]);
        m1 = fminf(m1, dptr[(size_t)(j + 1) * NPAD] * rinv[j + 1]);
        m2 = fminf(m2, dptr[(size_t)(j + 2) * NPAD] * rinv[j + 2]);
        m3 = fminf(m3, dptr[(size_t)(j + 3) * NPAD] * rinv[j + 3]);
    }
    g_CM[b * NPAD + i] = fminf(fminf(m0, m1), fminf(m2, m3));
}

// -------- final deterministic reduction -------------------------------------
__global__ void k_final(float* __restrict__ out) {
    __shared__ float sh[256];
    float acc = 0.0f;
    for (int idx = threadIdx.x; idx < NIMG * NPAD; idx += 256) {
        int i = idx & (NPAD - 1);
        if (i < NREAL) acc += g_CM[idx];
    }
    sh[threadIdx.x] = acc;
    __syncthreads();
    for (int s = 128; s > 0; s >>= 1) {
        if (threadIdx.x < s) sh[threadIdx.x] += sh[threadIdx.x + s];
        __syncthreads();
    }
    if (threadIdx.x == 0) out[0] = sh[0] * (1.0f / ((float)NIMG * (float)NREAL));
}

// -------- launch ------------------------------------------------------------
extern "C" void kernel_launch(void* const* d_in, const int* in_sizes, int n_in,
                              void* d_out, int out_size) {
    const float* x = (const float*)d_in[0];
    const float* y = (const float*)d_in[1];
    float* out = (float*)d_out;

    const int eblocks = (NIMG * DPAD * NPAD + 255) / 256;
    const int nblocks = (NIMG * NPAD + 255) / 256;

    k_extract<<<eblocks, 256>>>(x, 0);
    k_extract<<<eblocks, 256>>>(y, 1);
    k_norms<<<nblocks, 256>>>(0);
    k_norms<<<nblocks, 256>>>(1);
    k_init<<<nblocks, 256>>>();
    k_gemm_pass1<<<dim3(NPAD / 128, NPAD / 128, NIMG), 256>>>();
    k_rinv<<<nblocks, 256>>>();
    k_pass2<<<dim3(NPAD / 256, NIMG), 256>>>();
    k_final<<<1, 256>>>(out);
}

// round 7
// speedup vs baseline: 1.5058x; 1.5058x over previous
#include <cuda_runtime.h>
#include <stdint.h>

// Problem constants
#define NREAL 8100   // 90*90 valid patches per image
#define NPAD  8192   // padded patch count
#define DREAL 147    // 3*7*7
#define KS    160    // K storage stride per patch row in global (floats)
#define KSM   168    // K stride in smem (floats); 168%32=8 -> conflict-free LDS.64
#define NIMG  4
#define ALPHA_F 0.05f
#define JCHUNK 64    // Y rows per chunk
#define NCHUNK 128   // 8192/64 chunks

// -------- device scratch ----------------------------------------------------
// Layout note: k is stored PAIR-PERMUTED: within each 8-block, storage order is
// logical [0,4,1,5,2,6,3,7]. Applied to BOTH X and Y -> GEMM/norms unchanged,
// but mma fragment elements (t, t+4) become adjacent -> LDS.64 gathers.
__device__ float g_XP[NIMG * NPAD * KS];
__device__ float g_YP[NIMG * NPAD * KS];
__device__ float g_X2[NIMG * NPAD];
__device__ float g_Y2[NIMG * NPAD];
__device__ unsigned int g_RM[NIMG * NPAD]; // row mins (float bits, non-neg)
__device__ float g_RINV[NIMG * NPAD];
__device__ unsigned int g_CM[NIMG * NPAD]; // col mins (float bits)

__device__ __forceinline__ float finf() { return __int_as_float(0x7f800000); }

// tf32 round: cvt.rna.tf32.f32 requires a .b32 destination register
__device__ __forceinline__ float to_tf32(float v) {
    uint32_t u;
    asm("cvt.rna.tf32.f32 %0, %1;" : "=r"(u) : "f"(v));
    return __uint_as_float(u);
}

// tf32 warp MMA (sm_80+; assembles for plain sm_100 target)
#define MMA8(c0,c1,c2,c3,a0,a1,a2,a3,b0,b1) \
    asm volatile("mma.sync.aligned.m16n8k8.row.col.f32.tf32.tf32.f32 " \
        "{%0,%1,%2,%3}, {%4,%5,%6,%7}, {%8,%9}, {%0,%1,%2,%3};" \
        : "+f"(c0), "+f"(c1), "+f"(c2), "+f"(c3) \
        : "r"(a0), "r"(a1), "r"(a2), "r"(a3), "r"(b0), "r"(b1))

// SMEM: X tile [128][168]f, Y [64][168]f, RM stage, CM stage
#define SMF_X   0
#define SMF_Y   (128 * KSM)
#define SMB_RMS ((128 + JCHUNK) * KSM * 4)
#define SMB_CMS (SMB_RMS + 4 * 64 * 4)
#define SM_TOTAL (SMB_CMS + 128 * 4)     // 130,560 B

// -------- patch extraction: [b,c,h,w] -> [b][n][KS], tf32, k-pair-permuted --
__global__ void k_extract(const float* __restrict__ src, int which) {
    float* __restrict__ dst = which ? g_YP : g_XP;
    int idx = blockIdx.x * 256 + threadIdx.x;
    if (idx >= NIMG * NPAD * KS) return;
    int kq = idx % KS;                       // storage position
    int n  = (idx / KS) & (NPAD - 1);
    int b  = idx / (KS * NPAD);
    int q  = kq & 7;
    int k  = (kq & ~7) + ((q & 1) ? (q >> 1) + 4 : (q >> 1));  // logical k
    float v = 0.0f;
    if (k < DREAL && n < NREAL) {
        int c  = k / 49;
        int rr = (k % 49) / 7;
        int ss = k % 7;
        int oy = n / 90;
        int ox = n - oy * 90;
        v = to_tf32(src[(((b * 3 + c) * 96) + oy + rr) * 96 + ox + ss]);
    }
    dst[idx] = v;
}

// -------- squared norms (permutation-invariant) ------------------------------
__global__ void k_norms(int which) {
    const float* __restrict__ p = which ? g_YP : g_XP;
    float* __restrict__ out     = which ? g_Y2 : g_X2;
    int row  = blockIdx.x * 8 + (threadIdx.x >> 5);
    int lane = threadIdx.x & 31;
    const float4* r = (const float4*)(p + (size_t)row * KS);
    float4 v = r[lane];
    float s = v.x * v.x + v.y * v.y + v.z * v.z + v.w * v.w;
    if (lane < 8) {
        float4 w = r[32 + lane];
        s += w.x * w.x + w.y * w.y + w.z * w.z + w.w * w.w;
    }
#pragma unroll
    for (int off = 16; off > 0; off >>= 1)
        s += __shfl_xor_sync(0xffffffffu, s, off);
    if (lane == 0) out[row] = s;
}

__global__ void k_init() {
    int idx = blockIdx.x * 256 + threadIdx.x;
    if (idx < NIMG * NPAD) g_RM[idx] = 0x7f800000u;
}

// -------- persistent-tile GEMM pass. PASS 0: row-min. PASS 1: col-min. ------
// Grid (64, NIMG): CTA owns i-block [i0, i0+128), sweeps all j in 64-chunks.
template <int PASS>
__global__ void __launch_bounds__(256, 1) k_pass() {
    extern __shared__ char smem[];
    float* XS = (float*)smem + SMF_X;
    float* YS = (float*)smem + SMF_Y;
    unsigned int* RMS = (unsigned int*)(smem + SMB_RMS);  // [4 wi][64 j]
    unsigned int* CMS = (unsigned int*)(smem + SMB_CMS);  // [128 i]

    const int b   = blockIdx.y;
    const int i0  = blockIdx.x * 128;
    const int tid = threadIdx.x;
    const int lane = tid & 31;
    const int g = lane >> 2, t = lane & 3;   // mma group / thread-in-group
    const int wj = (tid >> 5) >> 2;          // 0..1 (j sub-block of 32)
    const int wi = (tid >> 5) & 3;           // 0..3 (i sub-block of 32)

    const float* Xg = g_XP + ((size_t)b * NPAD + i0) * KS;
    const float* Yg = g_YP + (size_t)b * NPAD * KS;

    if (PASS == 1 && tid < 128) CMS[tid] = 0x7f800000u;

    // load X tile: 128 rows x 40 float4 -> smem stride 42 float4
    {
        float4* X4 = (float4*)XS;
        const float4* G4 = (const float4*)Xg;
        for (int v = tid; v < 128 * 40; v += 256) {
            int r = v / 40, q = v - r * 40;
            X4[r * 42 + q] = G4[r * 40 + q];
        }
    }

    // x2 for my 8 columns (+inf marks padded i -> auto-excluded from mins)
    float x2r[4][2];
#pragma unroll
    for (int nf = 0; nf < 4; nf++)
#pragma unroll
        for (int p = 0; p < 2; p++) {
            int i = i0 + wi * 32 + nf * 8 + t * 2 + p;
            x2r[nf][p] = (i < NREAL) ? g_X2[b * NPAD + i] : finf();
        }

    float cm[4][2];
#pragma unroll
    for (int nf = 0; nf < 4; nf++) { cm[nf][0] = finf(); cm[nf][1] = finf(); }

    const float invD = 1.0f / (float)DREAL;
    const uint32_t* Xu = (const uint32_t*)XS;
    const uint32_t* Yu = (const uint32_t*)YS;
    float4* Y4 = (float4*)YS;

    for (int jt = 0; jt < NCHUNK; jt++) {
        __syncthreads();   // previous chunk compute done before overwrite
        {
            const float4* G4 = (const float4*)(Yg + (size_t)jt * JCHUNK * KS);
            for (int v = tid; v < JCHUNK * 40; v += 256) {
                int r = v / 40, q = v - r * 40;
                Y4[r * 42 + q] = G4[r * 40 + q];
            }
        }
        __syncthreads();

        // ---- 64x128 GEMM chunk: warp tile 32j x 32i, m16n8k8, 19 K-steps ----
        float c[2][4][4];
#pragma unroll
        for (int f = 0; f < 2; f++)
#pragma unroll
            for (int nf = 0; nf < 4; nf++)
#pragma unroll
                for (int k = 0; k < 4; k++) c[f][nf][k] = 0.0f;

#pragma unroll 4
        for (int kc = 0; kc < 152; kc += 8) {
            uint32_t a[2][4], bb[4][2];
#pragma unroll
            for (int f = 0; f < 2; f++) {
                int row = wj * 32 + f * 16 + g;
                uint2 lo = *(const uint2*)(Yu + row * KSM + kc + 2 * t);
                uint2 hi = *(const uint2*)(Yu + (row + 8) * KSM + kc + 2 * t);
                a[f][0] = lo.x; a[f][2] = lo.y;   // logical k=t, t+4
                a[f][1] = hi.x; a[f][3] = hi.y;
            }
#pragma unroll
            for (int nf = 0; nf < 4; nf++) {
                int col = wi * 32 + nf * 8 + g;
                uint2 bv = *(const uint2*)(Xu + col * KSM + kc + 2 * t);
                bb[nf][0] = bv.x; bb[nf][1] = bv.y;
            }
#pragma unroll
            for (int f = 0; f < 2; f++)
#pragma unroll
                for (int nf = 0; nf < 4; nf++)
                    MMA8(c[f][nf][0], c[f][nf][1], c[f][nf][2], c[f][nf][3],
                         a[f][0], a[f][1], a[f][2], a[f][3], bb[nf][0], bb[nf][1]);
        }

        // ---- epilogue for this chunk ----
        const int jbase = jt * JCHUNK + wj * 32;
        float y2v[2][2], rjv[2][2];
#pragma unroll
        for (int f = 0; f < 2; f++)
#pragma unroll
            for (int h = 0; h < 2; h++) {
                int j = jbase + f * 16 + h * 8 + g;
                y2v[f][h] = g_Y2[b * NPAD + j];
                if (PASS == 1)
                    rjv[f][h] = (j < NREAL) ? g_RINV[b * NPAD + j] : finf();
            }

        if (PASS == 0) {
            float rmin[2][2] = {{finf(), finf()}, {finf(), finf()}};
#pragma unroll
            for (int f = 0; f < 2; f++)
#pragma unroll
                for (int nf = 0; nf < 4; nf++)
#pragma unroll
                    for (int k = 0; k < 4; k++) {
                        float d = fmaxf((y2v[f][k >> 1] + x2r[nf][k & 1]
                                         - 2.0f * c[f][nf][k]) * invD, 0.0f);
                        rmin[f][k >> 1] = fminf(rmin[f][k >> 1], d);
                    }
#pragma unroll
            for (int f = 0; f < 2; f++)
#pragma unroll
                for (int h = 0; h < 2; h++) {
                    float m = rmin[f][h];
                    m = fminf(m, __shfl_xor_sync(0xffffffffu, m, 1));
                    m = fminf(m, __shfl_xor_sync(0xffffffffu, m, 2));
                    if (t == 0)
                        RMS[wi * 64 + wj * 32 + f * 16 + h * 8 + g] = __float_as_uint(m);
                }
            __syncthreads();
            if (tid < 64) {
                unsigned int m = min(min(RMS[tid], RMS[64 + tid]),
                                     min(RMS[128 + tid], RMS[192 + tid]));
                int j = jt * JCHUNK + tid;
                if (j < NREAL) atomicMin(&g_RM[b * NPAD + j], m);
            }
        } else {
#pragma unroll
            for (int f = 0; f < 2; f++)
#pragma unroll
                for (int nf = 0; nf < 4; nf++)
#pragma unroll
                    for (int k = 0; k < 4; k++) {
                        float d = fmaxf((y2v[f][k >> 1] + x2r[nf][k & 1]
                                         - 2.0f * c[f][nf][k]) * invD, 0.0f);
                        // invalid j: rjv=inf; 0*inf=NaN but fminf drops NaN
                        cm[nf][k & 1] = fminf(cm[nf][k & 1], d * rjv[f][k >> 1]);
                    }
        }
    }

    if (PASS == 1) {
        // all-reduce col-mins over mma groups (lanes differing in g)
#pragma unroll
        for (int nf = 0; nf < 4; nf++)
#pragma unroll
            for (int p = 0; p < 2; p++) {
                float m = cm[nf][p];
                m = fminf(m, __shfl_xor_sync(0xffffffffu, m, 4));
                m = fminf(m, __shfl_xor_sync(0xffffffffu, m, 8));
                m = fminf(m, __shfl_xor_sync(0xffffffffu, m, 16));
                cm[nf][p] = m;
            }
        if (lane < 4) {   // g==0 lanes; t==lane
#pragma unroll
            for (int nf = 0; nf < 4; nf++)
#pragma unroll
                for (int p = 0; p < 2; p++)
                    atomicMin(&CMS[wi * 32 + nf * 8 + lane * 2 + p],
                              __float_as_uint(cm[nf][p]));
        }
        __syncthreads();
        if (tid < 128) g_CM[b * NPAD + i0 + tid] = CMS[tid];  // CTA owns block
    }
}

__global__ void k_rinv() {
    int idx = blockIdx.x * 256 + threadIdx.x;
    if (idx >= NIMG * NPAD) return;
    int j = idx & (NPAD - 1);
    float rm = __uint_as_float(g_RM[idx]);
    g_RINV[idx] = (j < NREAL) ? 1.0f / (rm + ALPHA_F) : 0.0f;
}

__global__ void k_final(float* __restrict__ out) {
    __shared__ float sh[256];
    float acc = 0.0f;
    for (int idx = threadIdx.x; idx < NIMG * NPAD; idx += 256) {
        int i = idx & (NPAD - 1);
        if (i < NREAL) acc += __uint_as_float(g_CM[idx]);
    }
    sh[threadIdx.x] = acc;
    __syncthreads();
    for (int s = 128; s > 0; s >>= 1) {
        if (threadIdx.x < s) sh[threadIdx.x] += sh[threadIdx.x + s];
        __syncthreads();
    }
    if (threadIdx.x == 0) out[0] = sh[0] * (1.0f / ((float)NIMG * (float)NREAL));
}

// -------- launch ------------------------------------------------------------
extern "C" void kernel_launch(void* const* d_in, const int* in_sizes, int n_in,
                              void* d_out, int out_size) {
    const float* x = (const float*)d_in[0];
    const float* y = (const float*)d_in[1];
    float* out = (float*)d_out;

    cudaFuncSetAttribute(k_pass<0>, cudaFuncAttributeMaxDynamicSharedMemorySize, SM_TOTAL);
    cudaFuncSetAttribute(k_pass<1>, cudaFuncAttributeMaxDynamicSharedMemorySize, SM_TOTAL);

    const int eblocks = (NIMG * NPAD * KS + 255) / 256;
    const int nblocks = (NIMG * NPAD + 255) / 256;

    k_extract<<<eblocks, 256>>>(x, 0);
    k_extract<<<eblocks, 256>>>(y, 1);
    k_norms<<<NIMG * NPAD / 8, 256>>>(0);
    k_norms<<<NIMG * NPAD / 8, 256>>>(1);
    k_init<<<nblocks, 256>>>();
    dim3 grid(NPAD / 128, NIMG);
    k_pass<0><<<grid, 256, SM_TOTAL>>>();
    k_rinv<<<nblocks, 256>>>();
    k_pass<1><<<grid, 256, SM_TOTAL>>>();
    k_final<<<1, 256>>>(out);
}

// round 9
// speedup vs baseline: 3.9220x; 2.6046x over previous
#include <cuda_runtime.h>
#include <stdint.h>

// Problem constants
#define NREAL 8100   // 90*90 valid patches per image
#define NPAD  8192   // padded patch count
#define DREAL 147    // 3*7*7
#define KSG   160    // K storage per patch row in global (bf16 elems; 320 B)
#define NIMG  4
#define ALPHA_F 0.05f
#define JCHUNK 64
#define NCHUNK 128

// -------- device scratch ----------------------------------------------------
// k storage is PAIR-PERMUTED within each 16-block: storage s -> logical
// k = blk*16 + (p&1)*8 + (p>>1)*2 + (s&1), p = (s&15)>>1. Applied to BOTH
// X and Y -> dot products and norms unchanged; mma fragments become LDS.64.
__device__ uint16_t g_XP[NIMG * NPAD * KSG];   // bf16 bits
__device__ uint16_t g_YP[NIMG * NPAD * KSG];
__device__ float g_X2[NIMG * NPAD];
__device__ float g_Y2[NIMG * NPAD];
__device__ unsigned int g_RM[NIMG * NPAD];     // row mins (float bits)
__device__ float g_RINV[NIMG * NPAD];
__device__ unsigned int g_CM[NIMG * NPAD];     // col mins (float bits)

__device__ __forceinline__ float finf() { return __int_as_float(0x7f800000); }

__device__ __forceinline__ uint16_t to_bf16(float v) {
    uint16_t u;
    asm("cvt.rn.bf16.f32 %0, %1;" : "=h"(u) : "f"(v));
    return u;
}
__device__ __forceinline__ float bf16lo(uint32_t u) { return __uint_as_float(u << 16); }
__device__ __forceinline__ float bf16hi(uint32_t u) { return __uint_as_float(u & 0xFFFF0000u); }

// bf16 warp MMA, K=16 (sm_80+; legal on plain sm_100 target)
#define MMA16(c0,c1,c2,c3,a0,a1,a2,a3,b0,b1) \
    asm volatile("mma.sync.aligned.m16n8k16.row.col.f32.bf16.bf16.f32 " \
        "{%0,%1,%2,%3}, {%4,%5,%6,%7}, {%8,%9}, {%0,%1,%2,%3};" \
        : "+f"(c0), "+f"(c1), "+f"(c2), "+f"(c3) \
        : "r"(a0), "r"(a1), "r"(a2), "r"(a3), "r"(b0), "r"(b1))

// SMEM layout (bytes): X 128x352, Y single stage 64x352, RM, CM
#define SMB_X   0
#define SMB_Y   45056
#define SMB_RMS (45056 + 22528)
#define SMB_CMS (SMB_RMS + 1024)
#define SM_TOTAL (SMB_CMS + 512)     // 69120 B -> 2 CTAs/SM

// -------- patch extraction -> bf16, k-pair-permuted -------------------------
__global__ void k_extract(const float* __restrict__ src, int which) {
    uint16_t* __restrict__ dst = which ? g_YP : g_XP;
    int idx = blockIdx.x * 256 + threadIdx.x;
    if (idx >= NIMG * NPAD * KSG) return;
    int kq = idx % KSG;
    int n  = (idx / KSG) & (NPAD - 1);
    int b  = idx / (KSG * NPAD);
    int s = kq & 15, p = s >> 1;
    int k = (kq & ~15) + (p & 1) * 8 + (p >> 1) * 2 + (s & 1);  // logical k
    uint16_t v = 0;
    if (k < DREAL && n < NREAL) {
        int c  = k / 49;
        int rr = (k % 49) / 7;
        int ss = k % 7;
        int oy = n / 90;
        int ox = n - oy * 90;
        v = to_bf16(src[(((b * 3 + c) * 96) + oy + rr) * 96 + ox + ss]);
    }
    dst[idx] = v;
}

// -------- squared norms on the bf16 values (fp32 accumulate) ----------------
__global__ void k_norms(int which) {
    const uint16_t* __restrict__ p = which ? g_YP : g_XP;
    float* __restrict__ out        = which ? g_Y2 : g_X2;
    int row  = blockIdx.x * 8 + (threadIdx.x >> 5);
    int lane = threadIdx.x & 31;
    float s = 0.0f;
    if (lane < 20) {   // 20 x 16B chunks = 320 B row
        uint4 u = *(const uint4*)(p + (size_t)row * KSG + lane * 8);
        float f;
        f = bf16lo(u.x); s += f * f;  f = bf16hi(u.x); s += f * f;
        f = bf16lo(u.y); s += f * f;  f = bf16hi(u.y); s += f * f;
        f = bf16lo(u.z); s += f * f;  f = bf16hi(u.z); s += f * f;
        f = bf16lo(u.w); s += f * f;  f = bf16hi(u.w); s += f * f;
    }
#pragma unroll
    for (int off = 16; off > 0; off >>= 1)
        s += __shfl_xor_sync(0xffffffffu, s, off);
    if (lane == 0) out[row] = s;
}

__global__ void k_init() {
    int idx = blockIdx.x * 256 + threadIdx.x;
    if (idx < NIMG * NPAD) g_RM[idx] = 0x7f800000u;
}

// -------- persistent-tile GEMM pass. PASS 0: row-min. PASS 1: col-min. ------
// Grid (64, NIMG): CTA owns i-block, sweeps all j in 64-chunks.
// Pipelining WITHOUT cp.async: next chunk is LDG'd into registers while the
// current chunk computes from smem; STS after a sync. (cp.async kills the
// bench container in this harness; see R5/R6/R8 vs R7 evidence.)
template <int PASS>
__global__ void __launch_bounds__(256, 2) k_pass() {
    extern __shared__ char smem[];
    char* XS = smem + SMB_X;
    char* YS = smem + SMB_Y;
    unsigned int* RMS = (unsigned int*)(smem + SMB_RMS);
    unsigned int* CMS = (unsigned int*)(smem + SMB_CMS);

    const int b   = blockIdx.y;
    const int i0  = blockIdx.x * 128;
    const int tid = threadIdx.x;
    const int lane = tid & 31;
    const int g = lane >> 2, t = lane & 3;
    const int wj = (tid >> 5) >> 2;          // 0..1
    const int wi = (tid >> 5) & 3;           // 0..3

    const char* Xg = (const char*)(g_XP + ((size_t)b * NPAD + i0) * KSG);
    const char* Yg = (const char*)(g_YP + (size_t)b * NPAD * KSG);

    if (PASS == 1 && tid < 128) CMS[tid] = 0x7f800000u;

    // X tile: 128 rows x 20 float4 chunks, smem stride 352 B
    {
        float4* X4 = (float4*)XS;
        const float4* G4 = (const float4*)Xg;
        for (int v = tid; v < 128 * 20; v += 256) {
            int r = v / 20, q = v - r * 20;
            X4[r * 22 + q] = G4[r * 20 + q];
        }
    }
    // Y chunk 0 (each thread owns 5 float4 slots: v = tid + s*256)
    {
        float4* Y4 = (float4*)YS;
        const float4* G4 = (const float4*)Yg;
#pragma unroll
        for (int s = 0; s < 5; s++) {
            int v = tid + s * 256;
            int r = v / 20, q = v - r * 20;
            Y4[r * 22 + q] = G4[r * 20 + q];
        }
    }

    float x2r[4][2];
#pragma unroll
    for (int nf = 0; nf < 4; nf++)
#pragma unroll
        for (int p = 0; p < 2; p++) {
            int i = i0 + wi * 32 + nf * 8 + t * 2 + p;
            x2r[nf][p] = (i < NREAL) ? g_X2[b * NPAD + i] : finf();
        }

    float cm[4][2];
#pragma unroll
    for (int nf = 0; nf < 4; nf++) { cm[nf][0] = finf(); cm[nf][1] = finf(); }

    const float invD = 1.0f / (float)DREAL;
    __syncthreads();

    for (int jt = 0; jt < NCHUNK; jt++) {
        // prefetch next chunk into registers (latency hidden by compute below)
        float4 pf[5];
        if (jt + 1 < NCHUNK) {
            const float4* G4 = (const float4*)(Yg + (size_t)(jt + 1) * JCHUNK * 320);
#pragma unroll
            for (int s = 0; s < 5; s++) {
                int v = tid + s * 256;
                int r = v / 20, q = v - r * 20;
                pf[s] = G4[r * 20 + q];
            }
        }

        // ---- 64x128 chunk: warp tile 32j x 32i, m16n8k16 bf16, 10 K-steps ---
        float c[2][4][4];
#pragma unroll
        for (int f = 0; f < 2; f++)
#pragma unroll
            for (int nf = 0; nf < 4; nf++)
#pragma unroll
                for (int k = 0; k < 4; k++) c[f][nf][k] = 0.0f;

#pragma unroll
        for (int ks = 0; ks < 10; ks++) {
            uint32_t a[2][4], bb[4][2];
            const int ko = ks * 32 + t * 8;   // byte offset in row
#pragma unroll
            for (int f = 0; f < 2; f++) {
                int row = wj * 32 + f * 16 + g;
                uint2 lo = *(const uint2*)(YS + row * 352 + ko);
                uint2 hi = *(const uint2*)(YS + (row + 8) * 352 + ko);
                a[f][0] = lo.x; a[f][2] = lo.y;
                a[f][1] = hi.x; a[f][3] = hi.y;
            }
#pragma unroll
            for (int nf = 0; nf < 4; nf++) {
                int col = wi * 32 + nf * 8 + g;
                uint2 bv = *(const uint2*)(XS + col * 352 + ko);
                bb[nf][0] = bv.x; bb[nf][1] = bv.y;
            }
#pragma unroll
            for (int f = 0; f < 2; f++)
#pragma unroll
                for (int nf = 0; nf < 4; nf++)
                    MMA16(c[f][nf][0], c[f][nf][1], c[f][nf][2], c[f][nf][3],
                          a[f][0], a[f][1], a[f][2], a[f][3], bb[nf][0], bb[nf][1]);
        }

        // ---- epilogue ----
        const int jbase = jt * JCHUNK + wj * 32;
        float y2v[2][2], rjv[2][2];
#pragma unroll
        for (int f = 0; f < 2; f++)
#pragma unroll
            for (int h = 0; h < 2; h++) {
                int j = jbase + f * 16 + h * 8 + g;
                y2v[f][h] = g_Y2[b * NPAD + j];
                if (PASS == 1)
                    rjv[f][h] = (j < NREAL) ? g_RINV[b * NPAD + j] : finf();
            }

        if (PASS == 0) {
            float rmin[2][2] = {{finf(), finf()}, {finf(), finf()}};
#pragma unroll
            for (int f = 0; f < 2; f++)
#pragma unroll
                for (int nf = 0; nf < 4; nf++)
#pragma unroll
                    for (int k = 0; k < 4; k++) {
                        float d = fmaxf((y2v[f][k >> 1] + x2r[nf][k & 1]
                                         - 2.0f * c[f][nf][k]) * invD, 0.0f);
                        rmin[f][k >> 1] = fminf(rmin[f][k >> 1], d);
                    }
#pragma unroll
            for (int f = 0; f < 2; f++)
#pragma unroll
                for (int h = 0; h < 2; h++) {
                    float m = rmin[f][h];
                    m = fminf(m, __shfl_xor_sync(0xffffffffu, m, 1));
                    m = fminf(m, __shfl_xor_sync(0xffffffffu, m, 2));
                    if (t == 0)
                        RMS[wi * 64 + wj * 32 + f * 16 + h * 8 + g] = __float_as_uint(m);
                }
            __syncthreads();
            if (tid < 64) {
                unsigned int m = min(min(RMS[tid], RMS[64 + tid]),
                                     min(RMS[128 + tid], RMS[192 + tid]));
                int j = jt * JCHUNK + tid;
                if (j < NREAL) atomicMin(&g_RM[b * NPAD + j], m);
            }
        } else {
#pragma unroll
            for (int f = 0; f < 2; f++)
#pragma unroll
                for (int nf = 0; nf < 4; nf++)
#pragma unroll
                    for (int k = 0; k < 4; k++) {
                        float d = fmaxf((y2v[f][k >> 1] + x2r[nf][k & 1]
                                         - 2.0f * c[f][nf][k]) * invD, 0.0f);
                        // invalid j: rjv=inf; 0*inf=NaN but fminf drops NaN
                        cm[nf][k & 1] = fminf(cm[nf][k & 1], d * rjv[f][k >> 1]);
                    }
        }

        // commit prefetched chunk to smem
        __syncthreads();   // all reads of YS done
        if (jt + 1 < NCHUNK) {
            float4* Y4 = (float4*)YS;
#pragma unroll
            for (int s = 0; s < 5; s++) {
                int v = tid + s * 256;
                int r = v / 20, q = v - r * 20;
                Y4[r * 22 + q] = pf[s];
            }
        }
        __syncthreads();   // YS ready for next iteration
    }

    if (PASS == 1) {
#pragma unroll
        for (int nf = 0; nf < 4; nf++)
#pragma unroll
            for (int p = 0; p < 2; p++) {
                float m = cm[nf][p];
                m = fminf(m, __shfl_xor_sync(0xffffffffu, m, 4));
                m = fminf(m, __shfl_xor_sync(0xffffffffu, m, 8));
                m = fminf(m, __shfl_xor_sync(0xffffffffu, m, 16));
                cm[nf][p] = m;
            }
        if (lane < 4) {
#pragma unroll
            for (int nf = 0; nf < 4; nf++)
#pragma unroll
                for (int p = 0; p < 2; p++)
                    atomicMin(&CMS[wi * 32 + nf * 8 + lane * 2 + p],
                              __float_as_uint(cm[nf][p]));
        }
        __syncthreads();
        if (tid < 128) g_CM[b * NPAD + i0 + tid] = CMS[tid];
    }
}

__global__ void k_rinv() {
    int idx = blockIdx.x * 256 + threadIdx.x;
    if (idx >= NIMG * NPAD) return;
    int j = idx & (NPAD - 1);
    float rm = __uint_as_float(g_RM[idx]);
    g_RINV[idx] = (j < NREAL) ? 1.0f / (rm + ALPHA_F) : 0.0f;
}

__global__ void k_final(float* __restrict__ out) {
    __shared__ float sh[256];
    float acc = 0.0f;
    for (int idx = threadIdx.x; idx < NIMG * NPAD; idx += 256) {
        int i = idx & (NPAD - 1);
        if (i < NREAL) acc += __uint_as_float(g_CM[idx]);
    }
    sh[threadIdx.x] = acc;
    __syncthreads();
    for (int s = 128; s > 0; s >>= 1) {
        if (threadIdx.x < s) sh[threadIdx.x] += sh[threadIdx.x + s];
        __syncthreads();
    }
    if (threadIdx.x == 0) out[0] = sh[0] * (1.0f / ((float)NIMG * (float)NREAL));
}

// -------- launch ------------------------------------------------------------
extern "C" void kernel_launch(void* const* d_in, const int* in_sizes, int n_in,
                              void* d_out, int out_size) {
    const float* x = (const float*)d_in[0];
    const float* y = (const float*)d_in[1];
    float* out = (float*)d_out;

    cudaFuncSetAttribute(k_pass<0>, cudaFuncAttributeMaxDynamicSharedMemorySize, SM_TOTAL);
    cudaFuncSetAttribute(k_pass<1>, cudaFuncAttributeMaxDynamicSharedMemorySize, SM_TOTAL);

    const int eblocks = (NIMG * NPAD * KSG + 255) / 256;
    const int nblocks = (NIMG * NPAD + 255) / 256;

    k_extract<<<eblocks, 256>>>(x, 0);
    k_extract<<<eblocks, 256>>>(y, 1);
    k_norms<<<NIMG * NPAD / 8, 256>>>(0);
    k_norms<<<NIMG * NPAD / 8, 256>>>(1);
    k_init<<<nblocks, 256>>>();
    dim3 grid(NPAD / 128, NIMG);
    k_pass<0><<<grid, 256, SM_TOTAL>>>();
    k_rinv<<<nblocks, 256>>>();
    k_pass<1><<<grid, 256, SM_TOTAL>>>();
    k_final<<<1, 256>>>(out);
}